// round 16
// baseline (speedup 1.0000x reference)
#include <cuda_runtime.h>
#include <cuda_bf16.h>
#include <math.h>
#include <stdint.h>

// Problem constants
#define NROWS 2048
#define DIMW  512
#define NH    8
#define HD    64
#define O_SIZE  (NROWS * DIMW)
#define SI_SIZE (NROWS * NH * HD * HD)

// Scratch for projected Q, K, V (post-activation)
__device__ float g_QKV[3][NROWS * DIMW];

__device__ __forceinline__ uint32_t smem_u32(const void* p) {
    uint32_t a;
    asm("{ .reg .u64 t; cvta.to.shared.u64 t, %1; cvt.u32.u64 %0, t; }" : "=r"(a) : "l"(p));
    return a;
}
__device__ __forceinline__ void ldsm4(uint32_t* r, uint32_t addr) {
    asm volatile("ldmatrix.sync.aligned.m8n8.x4.shared.b16 {%0,%1,%2,%3}, [%4];"
                 : "=r"(r[0]), "=r"(r[1]), "=r"(r[2]), "=r"(r[3]) : "r"(addr));
}
__device__ __forceinline__ void ldsm2(uint32_t* r, uint32_t addr) {
    asm volatile("ldmatrix.sync.aligned.m8n8.x2.shared.b16 {%0,%1}, [%2];"
                 : "=r"(r[0]), "=r"(r[1]) : "r"(addr));
}
__device__ __forceinline__ void mma_bf16(float* d, const uint32_t* a, const uint32_t* b) {
    asm volatile(
        "mma.sync.aligned.m16n8k16.row.col.f32.bf16.bf16.f32 "
        "{%0,%1,%2,%3}, {%4,%5,%6,%7}, {%8,%9}, {%0,%1,%2,%3};"
        : "+f"(d[0]), "+f"(d[1]), "+f"(d[2]), "+f"(d[3])
        : "r"(a[0]), "r"(a[1]), "r"(a[2]), "r"(a[3]), "r"(b[0]), "r"(b[1]));
}

// fp32 -> bf16 hi/lo split, 4 elements at a time, stored as uint2 (8B)
static __device__ __forceinline__ void split_store4(float4 v, char* hip, char* lop) {
    __nv_bfloat162 h0 = __float22bfloat162_rn(make_float2(v.x, v.y));
    __nv_bfloat162 h1 = __float22bfloat162_rn(make_float2(v.z, v.w));
    float2 hf0 = __bfloat1622float2(h0);
    float2 hf1 = __bfloat1622float2(h1);
    __nv_bfloat162 l0 = __float22bfloat162_rn(make_float2(v.x - hf0.x, v.y - hf0.y));
    __nv_bfloat162 l1 = __float22bfloat162_rn(make_float2(v.z - hf1.x, v.w - hf1.y));
    uint2 hu, lu;
    hu.x = *reinterpret_cast<uint32_t*>(&h0);
    hu.y = *reinterpret_cast<uint32_t*>(&h1);
    lu.x = *reinterpret_cast<uint32_t*>(&l0);
    lu.y = *reinterpret_cast<uint32_t*>(&l1);
    *reinterpret_cast<uint2*>(hip) = hu;
    *reinterpret_cast<uint2*>(lop) = lu;
}

// ---------------------------------------------------------------------------
// Kernel 1: QKV projection via HMMA (mma.sync bf16, 3-term fp32 split)
//   C[m][n] = act( sum_k X[m][k] * W[n][k] + b[n] )
// Tile BM=128 x BN=128, BK=32 fp32 per chunk (16 chunks).
// Smem rows padded to 40 bf16 (80B): stride=20 banks -> ldmatrix conflict-free.
// ---------------------------------------------------------------------------
#define BM 128
#define BN 128
#define BK 32
#define KST 40          // bf16 row stride (80 bytes)
#define KSTB 80

__global__ __launch_bounds__(256) void qkv_mma_kernel(
    const float* __restrict__ Xq, const float* __restrict__ Xk, const float* __restrict__ Xv,
    const float* __restrict__ Wq, const float* __restrict__ bq,
    const float* __restrict__ Wk, const float* __restrict__ bk,
    const float* __restrict__ Wv, const float* __restrict__ bv)
{
    __shared__ __align__(16) __nv_bfloat16 Ah_s[BM * KST];
    __shared__ __align__(16) __nv_bfloat16 Al_s[BM * KST];
    __shared__ __align__(16) __nv_bfloat16 Bh_s[BN * KST];
    __shared__ __align__(16) __nv_bfloat16 Bl_s[BN * KST];

    const int tid = threadIdx.x;
    const int wid = tid >> 5;
    const int lid = tid & 31;
    const int warp_m = wid & 1;        // 2 warp-rows of 64
    const int warp_n = wid >> 1;       // 4 warp-cols of 32

    const int z  = blockIdx.z;
    const int m0 = blockIdx.x * BM;
    const int n0 = blockIdx.y * BN;

    const float* __restrict__ X  = (z == 0) ? Xq : ((z == 1) ? Xk : Xv);
    const float* __restrict__ W  = (z == 0) ? Wq : ((z == 1) ? Wk : Wv);
    const float* __restrict__ Bv = (z == 0) ? bq : ((z == 1) ? bk : bv);
    float* __restrict__ C = g_QKV[z];

    float acc[4][4][4];
    #pragma unroll
    for (int mi = 0; mi < 4; mi++)
        #pragma unroll
        for (int ni = 0; ni < 4; ni++)
            #pragma unroll
            for (int c = 0; c < 4; c++) acc[mi][ni][c] = 0.0f;

    // ldmatrix base addresses (conflict-free by 80B row stride)
    const uint32_t aAh = smem_u32(Ah_s) + (warp_m * 64 + (lid & 15)) * KSTB + ((lid & 16) ? 16 : 0);
    const uint32_t aAl = smem_u32(Al_s) + (warp_m * 64 + (lid & 15)) * KSTB + ((lid & 16) ? 16 : 0);
    const uint32_t aBh = smem_u32(Bh_s) + (warp_n * 32 + (lid & 7)) * KSTB + ((lid & 8) ? 16 : 0);
    const uint32_t aBl = smem_u32(Bl_s) + (warp_n * 32 + (lid & 7)) * KSTB + ((lid & 8) ? 16 : 0);

    for (int ko = 0; ko < DIMW / BK; ko++) {
        // ---- load fp32 tiles + split-convert to bf16 hi/lo in smem
        const float* Xb = X + (size_t)m0 * DIMW + ko * BK;
        const float* Wb = W + (size_t)n0 * DIMW + ko * BK;
        #pragma unroll
        for (int it = 0; it < 4; it++) {
            int f   = tid + it * 256;          // 0..1023 float4 slots
            int row = f >> 3;                  // 0..127
            int c4  = f & 7;                   // 0..7 (float4 within 32 k)
            float4 va = *(const float4*)(Xb + row * DIMW + c4 * 4);
            split_store4(va, (char*)Ah_s + row * KSTB + c4 * 8,
                             (char*)Al_s + row * KSTB + c4 * 8);
            float4 vb = *(const float4*)(Wb + row * DIMW + c4 * 4);
            split_store4(vb, (char*)Bh_s + row * KSTB + c4 * 8,
                             (char*)Bl_s + row * KSTB + c4 * 8);
        }
        __syncthreads();

        // ---- 2 k-steps of 16, 3 split terms each
        #pragma unroll
        for (int ks = 0; ks < 2; ks++) {
            uint32_t Ah[4][4], Al[4][4], Bh[4][2], Bl[4][2];
            #pragma unroll
            for (int mi = 0; mi < 4; mi++) {
                ldsm4(Ah[mi], aAh + mi * 16 * KSTB + ks * 32);
                ldsm4(Al[mi], aAl + mi * 16 * KSTB + ks * 32);
            }
            #pragma unroll
            for (int ni = 0; ni < 4; ni++) {
                ldsm2(Bh[ni], aBh + ni * 8 * KSTB + ks * 32);
                ldsm2(Bl[ni], aBl + ni * 8 * KSTB + ks * 32);
            }
            #pragma unroll
            for (int mi = 0; mi < 4; mi++)
                #pragma unroll
                for (int ni = 0; ni < 4; ni++) {
                    mma_bf16(acc[mi][ni], Ah[mi], Bh[ni]);
                    mma_bf16(acc[mi][ni], Ah[mi], Bl[ni]);
                    mma_bf16(acc[mi][ni], Al[mi], Bh[ni]);
                }
        }
        __syncthreads();
    }

    // ---- epilogue: bias + activation, direct stores (32B sectors per frag row)
    const int mrow = m0 + warp_m * 64 + (lid >> 2);
    const int ncol = n0 + warp_n * 32 + (lid & 3) * 2;
    #pragma unroll
    for (int ni = 0; ni < 4; ni++) {
        float2 bb = *(const float2*)&Bv[ncol + ni * 8];
        #pragma unroll
        for (int mi = 0; mi < 4; mi++) {
            #pragma unroll
            for (int half = 0; half < 2; half++) {
                float v0 = acc[mi][ni][half * 2 + 0] + bb.x;
                float v1 = acc[mi][ni][half * 2 + 1] + bb.y;
                if (z < 2) {
                    v0 = (v0 > 0.0f) ? v0 + 1.0f : expf(v0);
                    v1 = (v1 > 0.0f) ? v1 + 1.0f : expf(v1);
                }
                int row = mrow + mi * 16 + half * 8;
                *(float2*)&C[(size_t)row * DIMW + ncol + ni * 8] = make_float2(v0, v1);
            }
        }
    }
}

// ---------------------------------------------------------------------------
// Kernel 2: per-(n,h) state update + readout (memory-bound streaming over Si)
//   Zi_new = Zi + K;  Si_new = Si + K(x)V
//   out = (Q.Si + (Q.K) V) / (Q.Zi_new + eps)
// ---------------------------------------------------------------------------
__global__ __launch_bounds__(128) void recur_stream_kernel(
    const float* __restrict__ Si, const float* __restrict__ Zi, float* __restrict__ out)
{
    const int nh  = blockIdx.x;
    const int tid = threadIdx.x;

    __shared__ float Q_s[64], K_s[64], V_s[64], Zn_s[64];
    __shared__ float red[8 * 64];
    __shared__ float sc[2];

    float* __restrict__ outO  = out;
    float* __restrict__ outSi = out + O_SIZE;
    float* __restrict__ outZi = out + O_SIZE + SI_SIZE;

    const int vecbase = nh * HD;

    if (tid < 64) {
        float q = g_QKV[0][vecbase + tid];
        float k = g_QKV[1][vecbase + tid];
        float v = g_QKV[2][vecbase + tid];
        Q_s[tid] = q; K_s[tid] = k; V_s[tid] = v;
        float zn = Zi[vecbase + tid] + k;
        Zn_s[tid] = zn;
        outZi[vecbase + tid] = zn;
    }
    __syncthreads();

    if (tid < 32) {
        float pq = Q_s[tid] * Zn_s[tid] + Q_s[tid + 32] * Zn_s[tid + 32];
        float pk = Q_s[tid] * K_s[tid]  + Q_s[tid + 32] * K_s[tid + 32];
        #pragma unroll
        for (int off = 16; off; off >>= 1) {
            pq += __shfl_xor_sync(0xffffffffu, pq, off);
            pk += __shfl_xor_sync(0xffffffffu, pk, off);
        }
        if (tid == 0) { sc[0] = 1.0f / (pq + 1e-6f); sc[1] = pk; }
    }
    __syncthreads();

    const int mg = tid & 15;
    const int dg = tid >> 4;
    const float4* __restrict__ Si4 = (const float4*)(Si    + (size_t)nh * (HD * HD));
    float4* __restrict__       So4 = (float4*)      (outSi + (size_t)nh * (HD * HD));
    const float4 vv = *(const float4*)&V_s[mg * 4];

    // Batch all 8 Si loads first (MLP=8), streaming hint (no L2 reuse)
    float4 s[8];
    #pragma unroll
    for (int r = 0; r < 8; r++)
        s[r] = __ldcs(&Si4[(r * 8 + dg) * 16 + mg]);

    float4 a = make_float4(0.f, 0.f, 0.f, 0.f);
    #pragma unroll
    for (int r = 0; r < 8; r++) {
        int d = r * 8 + dg;
        float kd = K_s[d];
        float qd = Q_s[d];
        float4 sn;
        sn.x = fmaf(kd, vv.x, s[r].x);
        sn.y = fmaf(kd, vv.y, s[r].y);
        sn.z = fmaf(kd, vv.z, s[r].z);
        sn.w = fmaf(kd, vv.w, s[r].w);
        __stcs(&So4[d * 16 + mg], sn);
        a.x = fmaf(qd, s[r].x, a.x);
        a.y = fmaf(qd, s[r].y, a.y);
        a.z = fmaf(qd, s[r].z, a.z);
        a.w = fmaf(qd, s[r].w, a.w);
    }

    *(float4*)&red[dg * 64 + mg * 4] = a;
    __syncthreads();

    if (tid < 64) {
        float o = 0.0f;
        #pragma unroll
        for (int g = 0; g < 8; g++) o += red[g * 64 + tid];
        o = (o + sc[1] * V_s[tid]) * sc[0];
        outO[vecbase + tid] = o;
    }
}

// ---------------------------------------------------------------------------
// Launcher
// ---------------------------------------------------------------------------
extern "C" void kernel_launch(void* const* d_in, const int* in_sizes, int n_in,
                              void* d_out, int out_size) {
    (void)in_sizes; (void)n_in; (void)out_size;
    const float* query = (const float*)d_in[0];
    const float* key   = (const float*)d_in[1];
    const float* value = (const float*)d_in[2];
    const float* Si    = (const float*)d_in[3];
    const float* Zi    = (const float*)d_in[4];
    const float* Wq    = (const float*)d_in[5];
    const float* bq    = (const float*)d_in[6];
    const float* Wk    = (const float*)d_in[7];
    const float* bk    = (const float*)d_in[8];
    const float* Wv    = (const float*)d_in[9];
    const float* bv    = (const float*)d_in[10];
    float* out = (float*)d_out;

    dim3 grid(NROWS / BM, DIMW / BN, 3);
    qkv_mma_kernel<<<grid, 256>>>(query, key, value, Wq, bq, Wk, bk, Wv, bv);

    recur_stream_kernel<<<NROWS * NH, 128>>>(Si, Zi, out);
}

// round 17
// speedup vs baseline: 1.0213x; 1.0213x over previous
#include <cuda_runtime.h>
#include <cuda_bf16.h>
#include <math.h>
#include <stdint.h>

// Problem constants
#define NROWS 2048
#define DIMW  512
#define NH    8
#define HD    64
#define O_SIZE  (NROWS * DIMW)
#define SI_SIZE (NROWS * NH * HD * HD)

// Scratch for projected Q, K, V (post-activation)
__device__ float g_QKV[3][NROWS * DIMW];

__device__ __forceinline__ uint32_t smem_u32(const void* p) {
    uint32_t a;
    asm("{ .reg .u64 t; cvta.to.shared.u64 t, %1; cvt.u32.u64 %0, t; }" : "=r"(a) : "l"(p));
    return a;
}
__device__ __forceinline__ void ldsm4(uint32_t* r, uint32_t addr) {
    asm volatile("ldmatrix.sync.aligned.m8n8.x4.shared.b16 {%0,%1,%2,%3}, [%4];"
                 : "=r"(r[0]), "=r"(r[1]), "=r"(r[2]), "=r"(r[3]) : "r"(addr));
}
__device__ __forceinline__ void ldsm2(uint32_t* r, uint32_t addr) {
    asm volatile("ldmatrix.sync.aligned.m8n8.x2.shared.b16 {%0,%1}, [%2];"
                 : "=r"(r[0]), "=r"(r[1]) : "r"(addr));
}
__device__ __forceinline__ void mma_bf16(float* d, const uint32_t* a, const uint32_t* b) {
    asm volatile(
        "mma.sync.aligned.m16n8k16.row.col.f32.bf16.bf16.f32 "
        "{%0,%1,%2,%3}, {%4,%5,%6,%7}, {%8,%9}, {%0,%1,%2,%3};"
        : "+f"(d[0]), "+f"(d[1]), "+f"(d[2]), "+f"(d[3])
        : "r"(a[0]), "r"(a[1]), "r"(a[2]), "r"(a[3]), "r"(b[0]), "r"(b[1]));
}

// fp32 -> bf16 hi/lo split, 4 elements at a time, stored as uint2 (8B)
static __device__ __forceinline__ void split_store4(float4 v, char* hip, char* lop) {
    __nv_bfloat162 h0 = __float22bfloat162_rn(make_float2(v.x, v.y));
    __nv_bfloat162 h1 = __float22bfloat162_rn(make_float2(v.z, v.w));
    float2 hf0 = __bfloat1622float2(h0);
    float2 hf1 = __bfloat1622float2(h1);
    __nv_bfloat162 l0 = __float22bfloat162_rn(make_float2(v.x - hf0.x, v.y - hf0.y));
    __nv_bfloat162 l1 = __float22bfloat162_rn(make_float2(v.z - hf1.x, v.w - hf1.y));
    uint2 hu, lu;
    hu.x = *reinterpret_cast<uint32_t*>(&h0);
    hu.y = *reinterpret_cast<uint32_t*>(&h1);
    lu.x = *reinterpret_cast<uint32_t*>(&l0);
    lu.y = *reinterpret_cast<uint32_t*>(&l1);
    *reinterpret_cast<uint2*>(hip) = hu;
    *reinterpret_cast<uint2*>(lop) = lu;
}

// ---------------------------------------------------------------------------
// Kernel 1: QKV projection via HMMA, double-buffered smem + register prefetch.
//   C[m][n] = act( sum_k X[m][k] * W[n][k] + b[n] )
// Tile BM=128 x BN=128, BK=32 fp32 per chunk (16 chunks), 3-term bf16 split.
// Smem: 2 stages x {Ah,Al,Bh,Bl}, rows padded to 40 bf16 (80B, conflict-free).
// ---------------------------------------------------------------------------
#define BM 128
#define BN 128
#define BK 32
#define KST 40
#define KSTB 80
#define ARR_BYTES (128 * KSTB)        // 10240 per array
#define STG_BYTES (4 * ARR_BYTES)     // 40960 per stage
#define SMEM_BYTES (2 * STG_BYTES)    // 81920

__global__ __launch_bounds__(256, 2) void qkv_mma_kernel(
    const float* __restrict__ Xq, const float* __restrict__ Xk, const float* __restrict__ Xv,
    const float* __restrict__ Wq, const float* __restrict__ bq,
    const float* __restrict__ Wk, const float* __restrict__ bk,
    const float* __restrict__ Wv, const float* __restrict__ bv)
{
    extern __shared__ char smem[];

    const int tid = threadIdx.x;
    const int wid = tid >> 5;
    const int lid = tid & 31;
    const int warp_m = wid & 1;
    const int warp_n = wid >> 1;

    const int z  = blockIdx.z;
    const int m0 = blockIdx.x * BM;
    const int n0 = blockIdx.y * BN;

    const float* __restrict__ X  = (z == 0) ? Xq : ((z == 1) ? Xk : Xv);
    const float* __restrict__ W  = (z == 0) ? Wq : ((z == 1) ? Wk : Wv);
    const float* __restrict__ Bv = (z == 0) ? bq : ((z == 1) ? bk : bv);
    float* __restrict__ C = g_QKV[z];

    float acc[4][4][4];
    #pragma unroll
    for (int mi = 0; mi < 4; mi++)
        #pragma unroll
        for (int ni = 0; ni < 4; ni++)
            #pragma unroll
            for (int c = 0; c < 4; c++) acc[mi][ni][c] = 0.0f;

    // Per-thread convert-phase geometry (constant across chunks):
    // slot f = tid + it*256 -> row = f>>3, c4 = f&7
    int soff[4], goff[4];
    #pragma unroll
    for (int it = 0; it < 4; it++) {
        int f = tid + it * 256;
        int row = f >> 3, c4 = f & 7;
        soff[it] = row * KSTB + c4 * 8;      // smem byte offset within array
        goff[it] = row * DIMW + c4 * 4;      // gmem float offset within tile
    }

    // ldmatrix lane addresses (byte offset within a stage)
    const uint32_t sbase = smem_u32(smem);
    const uint32_t oAh = 0 * ARR_BYTES + (warp_m * 64 + (lid & 15)) * KSTB + ((lid & 16) ? 16 : 0);
    const uint32_t oAl = 1 * ARR_BYTES + (warp_m * 64 + (lid & 15)) * KSTB + ((lid & 16) ? 16 : 0);
    const uint32_t oBh = 2 * ARR_BYTES + (warp_n * 32 + (lid & 7)) * KSTB + ((lid & 8) ? 16 : 0);
    const uint32_t oBl = 3 * ARR_BYTES + (warp_n * 32 + (lid & 7)) * KSTB + ((lid & 8) ? 16 : 0);

    // ---- prologue: chunk 0 -> stage 0
    {
        const float* Xb = X + (size_t)m0 * DIMW;
        const float* Wb = W + (size_t)n0 * DIMW;
        #pragma unroll
        for (int it = 0; it < 4; it++) {
            float4 va = *(const float4*)(Xb + goff[it]);
            split_store4(va, smem + soff[it], smem + ARR_BYTES + soff[it]);
            float4 vb = *(const float4*)(Wb + goff[it]);
            split_store4(vb, smem + 2 * ARR_BYTES + soff[it], smem + 3 * ARR_BYTES + soff[it]);
        }
        __syncthreads();
    }

    float4 ra[4];
    #pragma unroll 1
    for (int ko = 0; ko < DIMW / BK; ko++) {
        const uint32_t stg = (uint32_t)(ko & 1) * STG_BYTES;

        // prefetch next A tile into registers (in flight during MMA)
        if (ko < 15) {
            const float* Xb = X + (size_t)m0 * DIMW + (ko + 1) * BK;
            #pragma unroll
            for (int it = 0; it < 4; it++)
                ra[it] = *(const float4*)(Xb + goff[it]);
        }

        // ---- MMA phase on stage `stg` (2 k-steps; Ah pass then Al pass)
        #pragma unroll
        for (int ks = 0; ks < 2; ks++) {
            uint32_t Af[4][4], Bf[2];
            #pragma unroll
            for (int mi = 0; mi < 4; mi++)
                ldsm4(Af[mi], sbase + stg + oAh + mi * 16 * KSTB + ks * 32);
            #pragma unroll
            for (int ni = 0; ni < 4; ni++) {
                ldsm2(Bf, sbase + stg + oBh + ni * 8 * KSTB + ks * 32);
                #pragma unroll
                for (int mi = 0; mi < 4; mi++) mma_bf16(acc[mi][ni], Af[mi], Bf);
                ldsm2(Bf, sbase + stg + oBl + ni * 8 * KSTB + ks * 32);
                #pragma unroll
                for (int mi = 0; mi < 4; mi++) mma_bf16(acc[mi][ni], Af[mi], Bf);
            }
            #pragma unroll
            for (int mi = 0; mi < 4; mi++)
                ldsm4(Af[mi], sbase + stg + oAl + mi * 16 * KSTB + ks * 32);
            #pragma unroll
            for (int ni = 0; ni < 4; ni++) {
                ldsm2(Bf, sbase + stg + oBh + ni * 8 * KSTB + ks * 32);
                #pragma unroll
                for (int mi = 0; mi < 4; mi++) mma_bf16(acc[mi][ni], Af[mi], Bf);
            }
        }

        // ---- convert phase: B loads first (hide L2 latency under A convert)
        if (ko < 15) {
            char* sn = smem + (((ko + 1) & 1) ? STG_BYTES : 0);
            const float* Wb = W + (size_t)n0 * DIMW + (ko + 1) * BK;
            float4 rb[4];
            #pragma unroll
            for (int it = 0; it < 4; it++)
                rb[it] = *(const float4*)(Wb + goff[it]);
            #pragma unroll
            for (int it = 0; it < 4; it++)
                split_store4(ra[it], sn + soff[it], sn + ARR_BYTES + soff[it]);
            #pragma unroll
            for (int it = 0; it < 4; it++)
                split_store4(rb[it], sn + 2 * ARR_BYTES + soff[it], sn + 3 * ARR_BYTES + soff[it]);
            __syncthreads();
        }
    }

    // ---- epilogue: bias + activation, direct stores
    const int mrow = m0 + warp_m * 64 + (lid >> 2);
    const int ncol = n0 + warp_n * 32 + (lid & 3) * 2;
    #pragma unroll
    for (int ni = 0; ni < 4; ni++) {
        float2 bb = *(const float2*)&Bv[ncol + ni * 8];
        #pragma unroll
        for (int mi = 0; mi < 4; mi++) {
            #pragma unroll
            for (int half = 0; half < 2; half++) {
                float v0 = acc[mi][ni][half * 2 + 0] + bb.x;
                float v1 = acc[mi][ni][half * 2 + 1] + bb.y;
                if (z < 2) {
                    v0 = (v0 > 0.0f) ? v0 + 1.0f : expf(v0);
                    v1 = (v1 > 0.0f) ? v1 + 1.0f : expf(v1);
                }
                int row = mrow + mi * 16 + half * 8;
                *(float2*)&C[(size_t)row * DIMW + ncol + ni * 8] = make_float2(v0, v1);
            }
        }
    }
}

// ---------------------------------------------------------------------------
// Kernel 2: per-(n,h) state update + readout (memory-bound streaming over Si)
//   Zi_new = Zi + K;  Si_new = Si + K(x)V
//   out = (Q.Si + (Q.K) V) / (Q.Zi_new + eps)
// ---------------------------------------------------------------------------
__global__ __launch_bounds__(128) void recur_stream_kernel(
    const float* __restrict__ Si, const float* __restrict__ Zi, float* __restrict__ out)
{
    const int nh  = blockIdx.x;
    const int tid = threadIdx.x;

    __shared__ float Q_s[64], K_s[64], V_s[64], Zn_s[64];
    __shared__ float red[8 * 64];
    __shared__ float sc[2];

    float* __restrict__ outO  = out;
    float* __restrict__ outSi = out + O_SIZE;
    float* __restrict__ outZi = out + O_SIZE + SI_SIZE;

    const int vecbase = nh * HD;

    if (tid < 64) {
        float q = g_QKV[0][vecbase + tid];
        float k = g_QKV[1][vecbase + tid];
        float v = g_QKV[2][vecbase + tid];
        Q_s[tid] = q; K_s[tid] = k; V_s[tid] = v;
        float zn = Zi[vecbase + tid] + k;
        Zn_s[tid] = zn;
        outZi[vecbase + tid] = zn;
    }
    __syncthreads();

    if (tid < 32) {
        float pq = Q_s[tid] * Zn_s[tid] + Q_s[tid + 32] * Zn_s[tid + 32];
        float pk = Q_s[tid] * K_s[tid]  + Q_s[tid + 32] * K_s[tid + 32];
        #pragma unroll
        for (int off = 16; off; off >>= 1) {
            pq += __shfl_xor_sync(0xffffffffu, pq, off);
            pk += __shfl_xor_sync(0xffffffffu, pk, off);
        }
        if (tid == 0) { sc[0] = 1.0f / (pq + 1e-6f); sc[1] = pk; }
    }
    __syncthreads();

    const int mg = tid & 15;
    const int dg = tid >> 4;
    const float4* __restrict__ Si4 = (const float4*)(Si    + (size_t)nh * (HD * HD));
    float4* __restrict__       So4 = (float4*)      (outSi + (size_t)nh * (HD * HD));
    const float4 vv = *(const float4*)&V_s[mg * 4];

    // Batch all 8 Si loads first (MLP=8), streaming hint (no L2 reuse)
    float4 s[8];
    #pragma unroll
    for (int r = 0; r < 8; r++)
        s[r] = __ldcs(&Si4[(r * 8 + dg) * 16 + mg]);

    float4 a = make_float4(0.f, 0.f, 0.f, 0.f);
    #pragma unroll
    for (int r = 0; r < 8; r++) {
        int d = r * 8 + dg;
        float kd = K_s[d];
        float qd = Q_s[d];
        float4 sn;
        sn.x = fmaf(kd, vv.x, s[r].x);
        sn.y = fmaf(kd, vv.y, s[r].y);
        sn.z = fmaf(kd, vv.z, s[r].z);
        sn.w = fmaf(kd, vv.w, s[r].w);
        __stcs(&So4[d * 16 + mg], sn);
        a.x = fmaf(qd, s[r].x, a.x);
        a.y = fmaf(qd, s[r].y, a.y);
        a.z = fmaf(qd, s[r].z, a.z);
        a.w = fmaf(qd, s[r].w, a.w);
    }

    *(float4*)&red[dg * 64 + mg * 4] = a;
    __syncthreads();

    if (tid < 64) {
        float o = 0.0f;
        #pragma unroll
        for (int g = 0; g < 8; g++) o += red[g * 64 + tid];
        o = (o + sc[1] * V_s[tid]) * sc[0];
        outO[vecbase + tid] = o;
    }
}

// ---------------------------------------------------------------------------
// Launcher
// ---------------------------------------------------------------------------
extern "C" void kernel_launch(void* const* d_in, const int* in_sizes, int n_in,
                              void* d_out, int out_size) {
    (void)in_sizes; (void)n_in; (void)out_size;
    const float* query = (const float*)d_in[0];
    const float* key   = (const float*)d_in[1];
    const float* value = (const float*)d_in[2];
    const float* Si    = (const float*)d_in[3];
    const float* Zi    = (const float*)d_in[4];
    const float* Wq    = (const float*)d_in[5];
    const float* bq    = (const float*)d_in[6];
    const float* Wk    = (const float*)d_in[7];
    const float* bk    = (const float*)d_in[8];
    const float* Wv    = (const float*)d_in[9];
    const float* bv    = (const float*)d_in[10];
    float* out = (float*)d_out;

    cudaFuncSetAttribute(qkv_mma_kernel,
                         cudaFuncAttributeMaxDynamicSharedMemorySize, SMEM_BYTES);
    dim3 grid(NROWS / BM, DIMW / BN, 3);
    qkv_mma_kernel<<<grid, 256, SMEM_BYTES>>>(query, key, value,
                                              Wq, bq, Wk, bk, Wv, bv);

    recur_stream_kernel<<<NROWS * NH, 128>>>(Si, Zi, out);
}